// round 16
// baseline (speedup 1.0000x reference)
#include <cuda_runtime.h>
#include <cuda_fp16.h>
#include <math.h>
#include <stdint.h>

// ---------------------------------------------------------------------------
// Gate_14293651161746 (round 15): split-E for 2 CTAs/SM.
//   GEMM CTA: 64 tokens x 128 experts (grid T/64 x 2), drains fp32 logits to
//   SMEM every k=256, epilogue writes global logits; separate gate kernel.
//   Numerics identical to R12/R14:
//     a = a0 + a1s/2048 ; 64*b = b0 + b1s/2048 (W presplit once)
//     accA = sum a0*b0 ; accB = sum (a0*b1s + a1s*b0)
//     logit = (accA + accB/2048)/64
// Output: [weights (T*8) fp32][indices (T*8) as fp32]
// ---------------------------------------------------------------------------

#define FULLMASK 0xFFFFFFFFu
#define RSCALE 2048.0f
#define RSCALE_INV (1.0f / 2048.0f)
#define BSCALE 64.0f
#define BSCALE_INV (1.0f / 64.0f)

#define DD 7168
#define EE 256
#define TMAX 8192

static __device__ __half g_B0[(size_t)EE * DD];   // RN16(64*w)
static __device__ __half g_B1[(size_t)EE * DD];   // RN16((64w - b0)*2048)
static __device__ float g_logits[(size_t)TMAX * EE];

// ---- SMEM layout (per CTA) ------------------------------------------------
// Stage buffer (fp16 tiles, rows padded to 40 halves = 80 B):
//   A0: 64 x 80B = 5120 (off 0) | A1s: 5120 (off 5120)
//   B0: 128 x 80B = 10240 (off 10240) | B1s: 10240 (off 20480)
// Two stages, then fp32 drain table [64][132].
#define STAGE_BYTES 30720
#define LOGITS_OFF  61440
#define SMEM_BYTES  (61440 + 64 * 132 * 4)   // 95232

__device__ __forceinline__ uint32_t smem_to_u32(const void* p) {
    uint32_t a;
    asm("{ .reg .u64 t; cvta.to.shared.u64 t, %1; cvt.u32.u64 %0, t; }" : "=r"(a) : "l"(p));
    return a;
}

#define LDM4(r, addr) \
    asm volatile("ldmatrix.sync.aligned.m8n8.x4.shared.b16 {%0,%1,%2,%3}, [%4];" \
                 : "=r"((r)[0]), "=r"((r)[1]), "=r"((r)[2]), "=r"((r)[3]) \
                 : "r"(addr))

#define MMA16816(c, a, b0, b1) \
    asm("mma.sync.aligned.m16n8k16.row.col.f32.f16.f16.f32 " \
        "{%0,%1,%2,%3}, {%4,%5,%6,%7}, {%8,%9}, {%0,%1,%2,%3};" \
        : "+f"((c)[0]), "+f"((c)[1]), "+f"((c)[2]), "+f"((c)[3]) \
        : "r"((a)[0]), "r"((a)[1]), "r"((a)[2]), "r"((a)[3]), \
          "r"(b0), "r"(b1))

// split one float4 into main fp16 quad + scaled-residual fp16 quad
__device__ __forceinline__ void split4s(float4 v, uint2& lo, uint2& hi) {
    __half a0 = __float2half_rn(v.x), b0 = __float2half_rn(v.y);
    __half c0 = __float2half_rn(v.z), d0 = __float2half_rn(v.w);
    __half a1 = __float2half_rn((v.x - __half2float(a0)) * RSCALE);
    __half b1 = __float2half_rn((v.y - __half2float(b0)) * RSCALE);
    __half c1 = __float2half_rn((v.z - __half2float(c0)) * RSCALE);
    __half d1 = __float2half_rn((v.w - __half2float(d0)) * RSCALE);
    lo.x = (uint32_t)__half_as_ushort(a0) | ((uint32_t)__half_as_ushort(b0) << 16);
    lo.y = (uint32_t)__half_as_ushort(c0) | ((uint32_t)__half_as_ushort(d0) << 16);
    hi.x = (uint32_t)__half_as_ushort(a1) | ((uint32_t)__half_as_ushort(b1) << 16);
    hi.y = (uint32_t)__half_as_ushort(c1) | ((uint32_t)__half_as_ushort(d1) << 16);
}

// ---- presplit W -> two fp16 planes ----------------------------------------
__global__ void __launch_bounds__(256)
presplit_kernel(const float* __restrict__ W, __half* __restrict__ B0,
                __half* __restrict__ B1, int n4) {
    int i = blockIdx.x * blockDim.x + threadIdx.x;
    if (i >= n4) return;
    float4 v = ((const float4*)W)[i];
    v.x *= BSCALE; v.y *= BSCALE; v.z *= BSCALE; v.w *= BSCALE;
    uint2 lo, hi;
    split4s(v, lo, hi);
    ((uint2*)B0)[i] = lo;
    ((uint2*)B1)[i] = hi;
}

// ---- GEMM: 64 tokens x 128 experts per CTA, 2 CTAs/SM ---------------------
__global__ void __launch_bounds__(256, 2)
gemm_kernel(const float* __restrict__ X, const __half* __restrict__ B0g,
            const __half* __restrict__ B1g, float* __restrict__ Lg,
            int T, int E, int D) {
    extern __shared__ char smem[];
    const uint32_t sb = smem_to_u32(smem);
    const int tid = threadIdx.x;
    const int lane = tid & 31;
    const int wid = tid >> 5;
    const int wm = wid >> 2;   // 0..1 -> 32-row slice
    const int wn = wid & 3;    // 0..3 -> 32-col slice (of 128)
    const int bm = blockIdx.x * 64;
    const int bn = blockIdx.y * 128;

    float* ls = (float*)(smem + LOGITS_OFF);   // [64][132] fp32 drain table
#pragma unroll
    for (int i = 0; i < 33; i++) ls[tid + i * 256] = 0.0f;

    float accA[2][4][4];
    float accB[2][4][4];
#pragma unroll
    for (int i = 0; i < 2; i++)
#pragma unroll
        for (int j = 0; j < 4; j++)
#pragma unroll
            for (int k = 0; k < 4; k++) { accA[i][j][k] = 0.0f; accB[i][j][k] = 0.0f; }

    // A staging: row = tid>>3 (+32/j), chunk col = (tid&7)*4 floats
    const int grow = tid >> 3;
    const int gcol = (tid & 7) * 4;
    const float* Ag = X + (size_t)(bm + grow) * D + gcol;
    const size_t jstride = (size_t)32 * D;
    const uint32_t sts_off = (uint32_t)(grow * 80 + (tid & 7) * 8);

    // B staging: 128 rows x 64B per plane; thread -> row tid>>1, 2x16B chunks
    const int brow = tid >> 1;
    const int hb = (tid & 1) * 16;    // half-index base within 32-half row
    const __half* B0p = B0g + (size_t)(bn + brow) * D + hb;
    const __half* B1p = B1g + (size_t)(bn + brow) * D + hb;
    const uint32_t bdst = (uint32_t)(brow * 80 + hb * 2);

    const int NS = D / 32;
    float4 ra[2];
    uint4 rb0[2], rb1[2];

    // ldmatrix per-thread base offsets (bytes within a stage buffer)
    const int q = lane >> 3;
    const uint32_t pa = (uint32_t)((wm * 32 + (q & 1) * 8 + (lane & 7)) * 80 + (q >> 1) * 16);
    const uint32_t pb = (uint32_t)((wn * 32 + ((q >> 1) & 1) * 8 + (lane & 7)) * 80 + (q & 1) * 16);

    // fragment element -> drain row/col
    const int drow = wm * 32 + (lane >> 2);
    const int dcol = wn * 32 + (lane & 3) * 2;

    // prologue LDG (stage 0)
#pragma unroll
    for (int j = 0; j < 2; j++) ra[j] = *(const float4*)(Ag + j * jstride);
#pragma unroll
    for (int j = 0; j < 2; j++) {
        rb0[j] = *(const uint4*)(B0p + j * 8);
        rb1[j] = *(const uint4*)(B1p + j * 8);
    }

    for (int s = 0; s < NS; s++) {
        const uint32_t boff = (uint32_t)((s & 1) * STAGE_BYTES);
        // ---- STS: A split fp32->fp16 pair; B raw 16B ---------------------
        {
            char* bufc = smem + boff;
#pragma unroll
            for (int j = 0; j < 2; j++) {
                uint2 lo, hi;
                split4s(ra[j], lo, hi);
                uint32_t o = sts_off + (uint32_t)j * (32 * 80);
                *(uint2*)(bufc + o) = lo;           // A0
                *(uint2*)(bufc + 5120 + o) = hi;    // A1s
            }
#pragma unroll
            for (int j = 0; j < 2; j++) {
                uint32_t o = bdst + (uint32_t)j * 16;
                *(uint4*)(bufc + 10240 + o) = rb0[j];   // B0
                *(uint4*)(bufc + 20480 + o) = rb1[j];   // B1s
            }
        }
        __syncthreads();

        // ---- LDG next stage (in flight during MMA) -----------------------
        if (s + 1 < NS) {
            const int k0 = (s + 1) * 32;
#pragma unroll
            for (int j = 0; j < 2; j++) ra[j] = *(const float4*)(Ag + k0 + j * jstride);
#pragma unroll
            for (int j = 0; j < 2; j++) {
                rb0[j] = *(const uint4*)(B0p + k0 + j * 8);
                rb1[j] = *(const uint4*)(B1p + k0 + j * 8);
            }
        }

        // ---- MMA over this stage: 2 k16-steps ----------------------------
        const uint32_t abase = sb + boff + pa;
        const uint32_t bbase = sb + boff + 10240 + pb;
#pragma unroll
        for (int ks = 0; ks < 2; ks++) {
            uint32_t a0f[2][4], a1f[2][4];
#pragma unroll
            for (int mt = 0; mt < 2; mt++) {
                uint32_t aaddr = abase + (uint32_t)(mt * 1280 + ks * 32);
                LDM4(a0f[mt], aaddr);
                LDM4(a1f[mt], aaddr + 5120);
            }
#pragma unroll
            for (int np = 0; np < 2; np++) {
                uint32_t b0f[4], b1f[4];
                uint32_t baddr = bbase + (uint32_t)(np * 1280 + ks * 32);
                LDM4(b0f, baddr);
                LDM4(b1f, baddr + 10240);
#pragma unroll
                for (int mt = 0; mt < 2; mt++) {
                    MMA16816(accA[mt][2 * np],     a0f[mt], b0f[0], b0f[1]);
                    MMA16816(accA[mt][2 * np + 1], a0f[mt], b0f[2], b0f[3]);
                }
#pragma unroll
                for (int mt = 0; mt < 2; mt++) {
                    MMA16816(accB[mt][2 * np],     a1f[mt], b0f[0], b0f[1]);
                    MMA16816(accB[mt][2 * np + 1], a1f[mt], b0f[2], b0f[3]);
                }
#pragma unroll
                for (int mt = 0; mt < 2; mt++) {
                    MMA16816(accB[mt][2 * np],     a0f[mt], b1f[0], b1f[1]);
                    MMA16816(accB[mt][2 * np + 1], a0f[mt], b1f[2], b1f[3]);
                }
            }
        }

        // ---- chunk drain every 8 stages (k=256): acc -> fp32 SMEM --------
        if ((s & 7) == 7) {
#pragma unroll
            for (int mt = 0; mt < 2; mt++) {
#pragma unroll
                for (int np = 0; np < 2; np++) {
#pragma unroll
                    for (int nt = 0; nt < 2; nt++) {
                        float* cA = accA[mt][2 * np + nt];
                        float* cB = accB[mt][2 * np + nt];
                        int row = drow + mt * 16;
                        int col = dcol + np * 16 + nt * 8;
                        ls[row * 132 + col]           += cA[0] + cB[0] * RSCALE_INV;
                        ls[row * 132 + col + 1]       += cA[1] + cB[1] * RSCALE_INV;
                        ls[(row + 8) * 132 + col]     += cA[2] + cB[2] * RSCALE_INV;
                        ls[(row + 8) * 132 + col + 1] += cA[3] + cB[3] * RSCALE_INV;
                        cA[0] = cA[1] = cA[2] = cA[3] = 0.0f;
                        cB[0] = cB[1] = cB[2] = cB[3] = 0.0f;
                    }
                }
            }
        }
        __syncthreads();
    }

    // ---- epilogue: each warp writes its own drained cells to global ------
#pragma unroll
    for (int mt = 0; mt < 2; mt++) {
#pragma unroll
        for (int np = 0; np < 2; np++) {
#pragma unroll
            for (int nt = 0; nt < 2; nt++) {
                int row = drow + mt * 16;
                int col = dcol + np * 16 + nt * 8;
#pragma unroll
                for (int h = 0; h < 2; h++) {
                    float2 v;
                    v.x = ls[(row + h * 8) * 132 + col];
                    v.y = ls[(row + h * 8) * 132 + col + 1];
                    *(float2*)(Lg + (size_t)(bm + row + h * 8) * EE + bn + col) = v;
                }
            }
        }
    }
}

// ---- gate: one warp per token (proven R12/R14 logic, global logits) -------
__global__ void __launch_bounds__(256)
gate_kernel(const float* __restrict__ Lg, const float* __restrict__ bias,
            float* __restrict__ outW, float* __restrict__ outI, int T) {
    const int token = (blockIdx.x * blockDim.x + threadIdx.x) >> 5;
    const int l = threadIdx.x & 31;
    if (token >= T) return;

    const float* Lp = Lg + (size_t)token * 256 + l * 8;
    float4 v0 = *(const float4*)Lp;
    float4 v1 = *(const float4*)(Lp + 4);
    float4 c0 = *(const float4*)(bias + l * 8);
    float4 c1 = *(const float4*)(bias + l * 8 + 4);
    float lg[8] = {v0.x, v0.y, v0.z, v0.w, v1.x, v1.y, v1.z, v1.w};
    const float bs[8] = {c0.x, c0.y, c0.z, c0.w, c1.x, c1.y, c1.z, c1.w};

    float sig[8], s[8];
#pragma unroll
    for (int j = 0; j < 8; j++) {
        float logit = lg[j] * BSCALE_INV;   // undo exact B pre-scale
        sig[j] = 1.0f / (1.0f + expf(-logit));
        s[j] = sig[j] + bs[j];
    }

    // per-lane top2, merged across the 4-lane quad (= one group)
    float t1 = -INFINITY, t2 = -INFINITY;
#pragma unroll
    for (int j = 0; j < 8; j++) {
        float v = s[j];
        if (v > t1) { t2 = t1; t1 = v; }
        else if (v > t2) { t2 = v; }
    }
#pragma unroll
    for (int off = 1; off < 4; off <<= 1) {
        float o1 = __shfl_xor_sync(FULLMASK, t1, off);
        float o2 = __shfl_xor_sync(FULLMASK, t2, off);
        float m1 = fmaxf(t1, o1);
        float m2 = fmaxf(fminf(t1, o1), (t1 > o1) ? t2 : o2);
        t1 = m1; t2 = m2;
    }
    float gsc = t1 + t2;

    float gs[8];
#pragma unroll
    for (int g = 0; g < 8; g++) gs[g] = __shfl_sync(FULLMASK, gsc, g * 4);

    int keepmask = 0;
#pragma unroll
    for (int rr = 0; rr < 4; rr++) {
        float best = -INFINITY; int bg = 0;
#pragma unroll
        for (int g = 0; g < 8; g++)
            if (!((keepmask >> g) & 1) && gs[g] > best) { best = gs[g]; bg = g; }
        keepmask |= 1 << bg;
    }
    const bool mk = (keepmask >> (l >> 2)) & 1;
    float sm[8];
#pragma unroll
    for (int j = 0; j < 8; j++) sm[j] = mk ? s[j] : 0.0f;

    int takenmask = 0;
    float wsel[8]; int isel[8]; float wsum = 0.0f;
#pragma unroll
    for (int rr = 0; rr < 8; rr++) {
        float bv = -INFINITY; int bi = 0x7FFFFFFF;
#pragma unroll
        for (int j = 0; j < 8; j++)
            if (!((takenmask >> j) & 1) && sm[j] > bv) { bv = sm[j]; bi = l * 8 + j; }
#pragma unroll
        for (int off = 16; off > 0; off >>= 1) {
            float ov = __shfl_xor_sync(FULLMASK, bv, off);
            int oi = __shfl_xor_sync(FULLMASK, bi, off);
            if (ov > bv || (ov == bv && oi < bi)) { bv = ov; bi = oi; }
        }
        const int wl = bi >> 3, wj = bi & 7;
        if (l == wl) takenmask |= 1 << wj;
        float selv = sig[0];
#pragma unroll
        for (int j = 1; j < 8; j++)
            if (j == wj) selv = sig[j];
        float wv = __shfl_sync(FULLMASK, selv, wl);
        wsel[rr] = wv; isel[rr] = bi; wsum += wv;
    }

    if (l == 0) {
        float inv = 1.0f / wsum;
#pragma unroll
        for (int rr = 0; rr < 8; rr++) {
            outW[(size_t)token * 8 + rr] = wsel[rr] * inv * 2.5f;
            outI[(size_t)token * 8 + rr] = (float)isel[rr];
        }
    }
}

// ------------------------------ launch -------------------------------------

extern "C" void kernel_launch(void* const* d_in, const int* in_sizes, int n_in,
                              void* d_out, int out_size) {
    const float* x = (const float*)d_in[0];       // [T, D]
    const float* weight = (const float*)d_in[1];  // [E, D]
    const float* bias = (const float*)d_in[2];    // [E]

    int E = in_sizes[2];           // 256
    int D = in_sizes[1] / E;       // 7168
    int T = in_sizes[0] / D;       // 8192

    void *pB0, *pB1, *pL;
    cudaGetSymbolAddress(&pB0, g_B0);
    cudaGetSymbolAddress(&pB1, g_B1);
    cudaGetSymbolAddress(&pL, g_logits);

    int n4 = E * D / 4;
    presplit_kernel<<<(n4 + 255) / 256, 256>>>(weight, (__half*)pB0, (__half*)pB1, n4);

    cudaFuncSetAttribute(gemm_kernel, cudaFuncAttributeMaxDynamicSharedMemorySize,
                         SMEM_BYTES);
    dim3 gg(T / 64, 2);
    gemm_kernel<<<gg, 256, SMEM_BYTES>>>(x, (const __half*)pB0, (const __half*)pB1,
                                         (float*)pL, T, E, D);

    float* outW = (float*)d_out;
    float* outI = (float*)d_out + (size_t)T * 8;
    gate_kernel<<<(T * 32 + 255) / 256, 256>>>((const float*)pL, bias, outW, outI, T);
}

// round 17
// speedup vs baseline: 1.0261x; 1.0261x over previous
#include <cuda_runtime.h>
#include <cuda_fp16.h>
#include <math.h>
#include <stdint.h>

// ---------------------------------------------------------------------------
// Gate_14293651161746 (round 17): R14 tile with 512 threads (16 warps).
//   Same 64x256 CTA tile, same SMEM layout, same numerics; warp tile 16x64.
//   W pre-split ONCE into two fp16 planes (64x main, 2048x residual scale).
//     a = a0 + a1s/2048 ; 64*b = b0 + b1s/2048
//     accA = sum a0*b0 ; accB = sum (a0*b1s + a1s*b0)
//     logit = (accA + accB/2048)/64, drained to fp32 SMEM every k=256
// Output: [weights (T*8) fp32][indices (T*8) as fp32]
// ---------------------------------------------------------------------------

#define FULLMASK 0xFFFFFFFFu
#define RSCALE 2048.0f
#define RSCALE_INV (1.0f / 2048.0f)
#define BSCALE 64.0f
#define BSCALE_INV (1.0f / 64.0f)

#define DD 7168
#define EE 256

static __device__ __half g_B0[(size_t)EE * DD];   // RN16(64*w)
static __device__ __half g_B1[(size_t)EE * DD];   // RN16((64w - b0)*2048)

// ---- SMEM layout (identical to R14) ---------------------------------------
//   A0: 64 x 80B = 5120 (off 0) | A1s: 5120 (off 5120)
//   B0: 256 x 80B = 20480 (off 10240) | B1s: 20480 (off 30720)
// Two stages, then fp32 logits accumulator [64][264].
#define STAGE_BYTES 51200
#define LOGITS_OFF  102400
#define SMEM_BYTES  (102400 + 64 * 264 * 4)   // 169984

__device__ __forceinline__ uint32_t smem_to_u32(const void* p) {
    uint32_t a;
    asm("{ .reg .u64 t; cvta.to.shared.u64 t, %1; cvt.u32.u64 %0, t; }" : "=r"(a) : "l"(p));
    return a;
}

#define LDM4(r, addr) \
    asm volatile("ldmatrix.sync.aligned.m8n8.x4.shared.b16 {%0,%1,%2,%3}, [%4];" \
                 : "=r"((r)[0]), "=r"((r)[1]), "=r"((r)[2]), "=r"((r)[3]) \
                 : "r"(addr))

#define MMA16816(c, a, b0, b1) \
    asm("mma.sync.aligned.m16n8k16.row.col.f32.f16.f16.f32 " \
        "{%0,%1,%2,%3}, {%4,%5,%6,%7}, {%8,%9}, {%0,%1,%2,%3};" \
        : "+f"((c)[0]), "+f"((c)[1]), "+f"((c)[2]), "+f"((c)[3]) \
        : "r"((a)[0]), "r"((a)[1]), "r"((a)[2]), "r"((a)[3]), \
          "r"(b0), "r"(b1))

// split one float4 into main fp16 quad + scaled-residual fp16 quad
__device__ __forceinline__ void split4s(float4 v, uint2& lo, uint2& hi) {
    __half a0 = __float2half_rn(v.x), b0 = __float2half_rn(v.y);
    __half c0 = __float2half_rn(v.z), d0 = __float2half_rn(v.w);
    __half a1 = __float2half_rn((v.x - __half2float(a0)) * RSCALE);
    __half b1 = __float2half_rn((v.y - __half2float(b0)) * RSCALE);
    __half c1 = __float2half_rn((v.z - __half2float(c0)) * RSCALE);
    __half d1 = __float2half_rn((v.w - __half2float(d0)) * RSCALE);
    lo.x = (uint32_t)__half_as_ushort(a0) | ((uint32_t)__half_as_ushort(b0) << 16);
    lo.y = (uint32_t)__half_as_ushort(c0) | ((uint32_t)__half_as_ushort(d0) << 16);
    hi.x = (uint32_t)__half_as_ushort(a1) | ((uint32_t)__half_as_ushort(b1) << 16);
    hi.y = (uint32_t)__half_as_ushort(c1) | ((uint32_t)__half_as_ushort(d1) << 16);
}

// ---- presplit W -> two fp16 planes ----------------------------------------
__global__ void __launch_bounds__(256)
presplit_kernel(const float* __restrict__ W, __half* __restrict__ B0,
                __half* __restrict__ B1, int n4) {
    int i = blockIdx.x * blockDim.x + threadIdx.x;
    if (i >= n4) return;
    float4 v = ((const float4*)W)[i];
    v.x *= BSCALE; v.y *= BSCALE; v.z *= BSCALE; v.w *= BSCALE;
    uint2 lo, hi;
    split4s(v, lo, hi);
    ((uint2*)B0)[i] = lo;
    ((uint2*)B1)[i] = hi;
}

__global__ void __launch_bounds__(512, 1)
moe_gate_kernel(const float* __restrict__ X, const __half* __restrict__ B0g,
                const __half* __restrict__ B1g, const float* __restrict__ bias,
                float* __restrict__ outW, float* __restrict__ outI,
                int T, int E, int D) {
    extern __shared__ char smem[];
    const uint32_t sb = smem_to_u32(smem);
    const int tid = threadIdx.x;
    const int lane = tid & 31;
    const int wid = tid >> 5;          // 0..15
    const int wm = wid >> 2;           // 0..3 -> 16-row slice
    const int wn = wid & 3;            // 0..3 -> 64-col slice
    const int bm = blockIdx.x * 64;

    float* ls = (float*)(smem + LOGITS_OFF);   // [64][264] fp32 logits accumulator
#pragma unroll
    for (int i = 0; i < 33; i++) ls[tid + i * 512] = 0.0f;

    float accA[8][4];
    float accB[8][4];
#pragma unroll
    for (int j = 0; j < 8; j++)
#pragma unroll
        for (int k = 0; k < 4; k++) { accA[j][k] = 0.0f; accB[j][k] = 0.0f; }

    // A staging: 64 rows x 8 float4 chunks = 512 threads exactly
    const int grow = tid >> 3;             // 0..63
    const int gcol = (tid & 7) * 4;
    const float* Ag = X + (size_t)(bm + grow) * D + gcol;
    const uint32_t sts_off = (uint32_t)(grow * 80 + (tid & 7) * 8);

    // B staging: per plane 256 rows x 64B; thread -> row tid>>1, 32B half-row
    const int brow = tid >> 1;             // 0..255
    const int hb = (tid & 1) * 16;         // half index base (0 or 16)
    const __half* B0p = B0g + (size_t)brow * D + hb;
    const __half* B1p = B1g + (size_t)brow * D + hb;
    const uint32_t bdst = (uint32_t)(brow * 80 + hb * 2);

    const int NS = D / 32;
    float4 ra;
    uint4 rb0[2], rb1[2];

    // ldmatrix per-thread base offsets (bytes within a stage buffer)
    const int q = lane >> 3;
    const uint32_t pa = (uint32_t)((wm * 16 + (q & 1) * 8 + (lane & 7)) * 80 + (q >> 1) * 16);
    const uint32_t pb = (uint32_t)((wn * 64 + ((q >> 1) & 1) * 8 + (lane & 7)) * 80 + (q & 1) * 16);

    // fragment element -> logits row/col (for chunk drains)
    const int drow = wm * 16 + (lane >> 2);
    const int dcol = wn * 64 + (lane & 3) * 2;

    // prologue LDG (stage 0)
    ra = *(const float4*)Ag;
#pragma unroll
    for (int j = 0; j < 2; j++) {
        rb0[j] = *(const uint4*)(B0p + j * 8);
        rb1[j] = *(const uint4*)(B1p + j * 8);
    }

    for (int s = 0; s < NS; s++) {
        const uint32_t boff = (uint32_t)((s & 1) * STAGE_BYTES);
        // ---- STS: A split fp32->fp16 pair; B raw 16B ---------------------
        {
            char* bufc = smem + boff;
            uint2 lo, hi;
            split4s(ra, lo, hi);
            *(uint2*)(bufc + sts_off) = lo;           // A0
            *(uint2*)(bufc + 5120 + sts_off) = hi;    // A1s
#pragma unroll
            for (int j = 0; j < 2; j++) {
                uint32_t o = bdst + (uint32_t)j * 16;
                *(uint4*)(bufc + 10240 + o) = rb0[j];   // B0
                *(uint4*)(bufc + 30720 + o) = rb1[j];   // B1s
            }
        }
        __syncthreads();

        // ---- LDG next stage (in flight during MMA) -----------------------
        if (s + 1 < NS) {
            const int k0 = (s + 1) * 32;
            ra = *(const float4*)(Ag + k0);
#pragma unroll
            for (int j = 0; j < 2; j++) {
                rb0[j] = *(const uint4*)(B0p + k0 + j * 8);
                rb1[j] = *(const uint4*)(B1p + k0 + j * 8);
            }
        }

        // ---- MMA over this stage: 2 k16-steps ----------------------------
        const uint32_t abase = sb + boff + pa;
        const uint32_t bbase = sb + boff + 10240 + pb;
#pragma unroll
        for (int ks = 0; ks < 2; ks++) {
            uint32_t a0f[4], a1f[4];
            uint32_t aaddr = abase + (uint32_t)(ks * 32);
            LDM4(a0f, aaddr);
            LDM4(a1f, aaddr + 5120);
#pragma unroll
            for (int np = 0; np < 4; np++) {
                uint32_t b0f[4], b1f[4];
                uint32_t baddr = bbase + (uint32_t)(np * 1280 + ks * 32);
                LDM4(b0f, baddr);
                LDM4(b1f, baddr + 20480);
                MMA16816(accA[2 * np],     a0f, b0f[0], b0f[1]);
                MMA16816(accA[2 * np + 1], a0f, b0f[2], b0f[3]);
                MMA16816(accB[2 * np],     a1f, b0f[0], b0f[1]);
                MMA16816(accB[2 * np + 1], a1f, b0f[2], b0f[3]);
                MMA16816(accB[2 * np],     a0f, b1f[0], b1f[1]);
                MMA16816(accB[2 * np + 1], a0f, b1f[2], b1f[3]);
            }
        }

        // ---- chunk drain every 8 stages (k=256): acc -> fp32 SMEM --------
        if ((s & 7) == 7) {
#pragma unroll
            for (int np = 0; np < 4; np++) {
#pragma unroll
                for (int nt = 0; nt < 2; nt++) {
                    float* cA = accA[2 * np + nt];
                    float* cB = accB[2 * np + nt];
                    int col = dcol + np * 16 + nt * 8;
                    ls[drow * 264 + col]           += cA[0] + cB[0] * RSCALE_INV;
                    ls[drow * 264 + col + 1]       += cA[1] + cB[1] * RSCALE_INV;
                    ls[(drow + 8) * 264 + col]     += cA[2] + cB[2] * RSCALE_INV;
                    ls[(drow + 8) * 264 + col + 1] += cA[3] + cB[3] * RSCALE_INV;
                    cA[0] = cA[1] = cA[2] = cA[3] = 0.0f;
                    cB[0] = cB[1] = cB[2] = cB[3] = 0.0f;
                }
            }
        }
        __syncthreads();
    }

    // ---- gate: one warp per token, 4 tokens per warp ----------------------
    float4 c0 = *(const float4*)(bias + lane * 8);
    float4 c1 = *(const float4*)(bias + lane * 8 + 4);
    const float bs[8] = {c0.x, c0.y, c0.z, c0.w, c1.x, c1.y, c1.z, c1.w};

    for (int r = 0; r < 4; r++) {
        const int tl = r * 16 + wid;
        const float* Lp = ls + tl * 264 + lane * 8;
        float4 v0 = *(const float4*)Lp;
        float4 v1 = *(const float4*)(Lp + 4);
        float lg[8] = {v0.x, v0.y, v0.z, v0.w, v1.x, v1.y, v1.z, v1.w};

        float sig[8], s[8];
#pragma unroll
        for (int j = 0; j < 8; j++) {
            float logit = lg[j] * BSCALE_INV;      // undo exact B pre-scale
            sig[j] = 1.0f / (1.0f + expf(-logit));
            s[j] = sig[j] + bs[j];
        }

        float t1 = -INFINITY, t2 = -INFINITY;
#pragma unroll
        for (int j = 0; j < 8; j++) {
            float v = s[j];
            if (v > t1) { t2 = t1; t1 = v; }
            else if (v > t2) { t2 = v; }
        }
#pragma unroll
        for (int off = 1; off < 4; off <<= 1) {
            float o1 = __shfl_xor_sync(FULLMASK, t1, off);
            float o2 = __shfl_xor_sync(FULLMASK, t2, off);
            float m1 = fmaxf(t1, o1);
            float m2 = fmaxf(fminf(t1, o1), (t1 > o1) ? t2 : o2);
            t1 = m1; t2 = m2;
        }
        float gsc = t1 + t2;

        float gs[8];
#pragma unroll
        for (int g = 0; g < 8; g++) gs[g] = __shfl_sync(FULLMASK, gsc, g * 4);

        int keepmask = 0;
#pragma unroll
        for (int rr = 0; rr < 4; rr++) {
            float best = -INFINITY; int bg = 0;
#pragma unroll
            for (int g = 0; g < 8; g++)
                if (!((keepmask >> g) & 1) && gs[g] > best) { best = gs[g]; bg = g; }
            keepmask |= 1 << bg;
        }
        const bool mk = (keepmask >> (lane >> 2)) & 1;
        float sm[8];
#pragma unroll
        for (int j = 0; j < 8; j++) sm[j] = mk ? s[j] : 0.0f;

        int takenmask = 0;
        float wsel[8]; int isel[8]; float wsum = 0.0f;
#pragma unroll
        for (int rr = 0; rr < 8; rr++) {
            float bv = -INFINITY; int bi = 0x7FFFFFFF;
#pragma unroll
            for (int j = 0; j < 8; j++)
                if (!((takenmask >> j) & 1) && sm[j] > bv) { bv = sm[j]; bi = lane * 8 + j; }
#pragma unroll
            for (int off = 16; off > 0; off >>= 1) {
                float ov = __shfl_xor_sync(FULLMASK, bv, off);
                int oi = __shfl_xor_sync(FULLMASK, bi, off);
                if (ov > bv || (ov == bv && oi < bi)) { bv = ov; bi = oi; }
            }
            const int wl = bi >> 3, wj = bi & 7;
            if (lane == wl) takenmask |= 1 << wj;
            float selv = sig[0];
#pragma unroll
            for (int j = 1; j < 8; j++)
                if (j == wj) selv = sig[j];
            float wv = __shfl_sync(FULLMASK, selv, wl);
            wsel[rr] = wv; isel[rr] = bi; wsum += wv;
        }

        if (lane == 0) {
            const int token = bm + tl;
            float inv = 1.0f / wsum;
#pragma unroll
            for (int rr = 0; rr < 8; rr++) {
                outW[(size_t)token * 8 + rr] = wsel[rr] * inv * 2.5f;
                outI[(size_t)token * 8 + rr] = (float)isel[rr];
            }
        }
    }
}

// ------------------------------ launch -------------------------------------

extern "C" void kernel_launch(void* const* d_in, const int* in_sizes, int n_in,
                              void* d_out, int out_size) {
    const float* x = (const float*)d_in[0];       // [T, D]
    const float* weight = (const float*)d_in[1];  // [E, D]
    const float* bias = (const float*)d_in[2];    // [E]

    int E = in_sizes[2];           // 256
    int D = in_sizes[1] / E;       // 7168
    int T = in_sizes[0] / D;       // 8192

    void *pB0, *pB1;
    cudaGetSymbolAddress(&pB0, g_B0);
    cudaGetSymbolAddress(&pB1, g_B1);

    int n4 = E * D / 4;
    presplit_kernel<<<(n4 + 255) / 256, 256>>>(weight, (__half*)pB0, (__half*)pB1, n4);

    float* outW = (float*)d_out;
    float* outI = (float*)d_out + (size_t)T * 8;

    cudaFuncSetAttribute(moe_gate_kernel, cudaFuncAttributeMaxDynamicSharedMemorySize,
                         SMEM_BYTES);
    moe_gate_kernel<<<T / 64, 512, SMEM_BYTES>>>(x, (const __half*)pB0, (const __half*)pB1,
                                                 bias, outW, outI, T, E, D);
}